// round 13
// baseline (speedup 1.0000x reference)
#include <cuda_runtime.h>
#include <cstdint>

// ---------------------------------------------------------------------------
// QuantLinear via dual-int8 IMMA (m16n8k32.s8.u8), exact decomposition.
//   x ~= S_b*(x0 + x1/254);  W = s*(q - z), q in 0..15
//   out[b,t] = Sr * sum_g [ s_g*P0_g + (s_g/254)*P1_g ]  +  C[b,t]
//   C[b,t]   = bias[t] - S_b * sum_g (s_g*z_g)[t] * Xe[g,b],  Xe = X0 + X1/254
// R13: per-component folds (no P*=254 barrier), z*X correction hoisted into a
//      separate rank-32 kernel; GEMM epilogue is read-modify-write on out.
// ---------------------------------------------------------------------------

#define MDIM 4096
#define KDIM 4096
#define NSG  32
#define NTH  256

__device__ uint32_t g_xp0[MDIM * 1024];
__device__ uint32_t g_xp1[MDIM * 1024];
__device__ float    g_Xe[NSG * MDIM];       // X0 + X1/254 per [g][b]
__device__ float    g_S[MDIM];

// ---------------- kernel 1: quantize + permute-pack ----------------
__global__ void __launch_bounds__(128)
quant_kernel(const float* __restrict__ x) {
    __shared__ float red[128];
    __shared__ int   ss0[128], ss1[128];
    const int b = blockIdx.x, tid = threadIdx.x;
    const float* xr = x + (size_t)b * KDIM + tid * 32;

    float v[32]; float mx = 0.f;
    #pragma unroll
    for (int i = 0; i < 32; ++i) { v[i] = xr[i]; mx = fmaxf(mx, fabsf(v[i])); }
    red[tid] = mx; __syncthreads();
    for (int o = 64; o > 0; o >>= 1) {
        if (tid < o) red[tid] = fmaxf(red[tid], red[tid + o]);
        __syncthreads();
    }
    const float S    = fmaxf(red[0], 1e-20f) * (1.f / 127.f);
    const float invS = 1.f / S;

    int q0[32], q1[32]; int s0 = 0, s1 = 0;
    #pragma unroll
    for (int i = 0; i < 32; ++i) {
        int a = __float2int_rn(v[i] * invS);
        a = max(-127, min(127, a));
        float r = v[i] - S * (float)a;
        int c = __float2int_rn(r * (254.f * invS));
        c = max(-127, min(127, c));
        q0[i] = a; q1[i] = c; s0 += a; s1 += c;
    }
    // word w' = kq*2 + half; byte j <- local k = (kq>>1)*8 + (kq&1) + 2j + 16*half
    const uint32_t base = (uint32_t)b * 1024u + tid * 8u;
    #pragma unroll
    for (int w = 0; w < 8; ++w) {
        const int kq = w >> 1, half = w & 1;
        const int k0 = (kq >> 1) * 8 + (kq & 1) + 16 * half;
        uint32_t u0 = 0, u1 = 0;
        #pragma unroll
        for (int j = 0; j < 4; ++j) {
            u0 |= (uint32_t)(q0[k0 + 2 * j] & 255) << (8 * j);
            u1 |= (uint32_t)(q1[k0 + 2 * j] & 255) << (8 * j);
        }
        g_xp0[base + w] = u0; g_xp1[base + w] = u1;
    }
    ss0[tid] = s0; ss1[tid] = s1; __syncthreads();
    if (tid < 32) {
        int X0 = ss0[4 * tid] + ss0[4 * tid + 1] + ss0[4 * tid + 2] + ss0[4 * tid + 3];
        int X1 = ss1[4 * tid] + ss1[4 * tid + 1] + ss1[4 * tid + 2] + ss1[4 * tid + 3];
        g_Xe[tid * MDIM + b] = (float)X0 + (float)X1 * (1.f / 254.f);
    }
    if (tid == 0) g_S[b] = S;
}

// ---------------- kernel 1.5: rank-32 correction  out = bias - S*sum sz*Xe ----
__global__ void __launch_bounds__(256)
corr_kernel(const float* __restrict__ scales,
            const float* __restrict__ zeros,
            const float* __restrict__ bias,
            float*       __restrict__ out,
            int T)
{
    __shared__ float sxe[32 * 64];   // Xe[g][b-local]
    __shared__ float ssz[32 * 64];   // (s*z)[g][t-local]
    const int tid = threadIdx.x;
    const int t0 = blockIdx.x * 64;
    const int b0 = blockIdx.y * 64;

    #pragma unroll
    for (int i = 0; i < 8; ++i) {
        int idx = tid + i * 256;          // 0..2047
        int g = idx >> 6, j = idx & 63;
        sxe[idx] = g_Xe[g * MDIM + b0 + j];
        ssz[idx] = scales[(size_t)g * T + t0 + j] * zeros[(size_t)g * T + t0 + j];
    }
    __syncthreads();

    const int b  = tid >> 2;              // 0..63
    const int c0 = (tid & 3) * 16;        // 0,16,32,48
    const float Sb = g_S[b0 + b];

    float acc[16];
    #pragma unroll
    for (int i = 0; i < 16; ++i) acc[i] = 0.f;
    for (int g = 0; g < 32; ++g) {
        const float xv = sxe[g * 64 + b];
        #pragma unroll
        for (int j = 0; j < 4; ++j) {
            float4 z4 = *(float4*)&ssz[g * 64 + c0 + 4 * j];
            acc[4 * j + 0] = fmaf(xv, z4.x, acc[4 * j + 0]);
            acc[4 * j + 1] = fmaf(xv, z4.y, acc[4 * j + 1]);
            acc[4 * j + 2] = fmaf(xv, z4.z, acc[4 * j + 2]);
            acc[4 * j + 3] = fmaf(xv, z4.w, acc[4 * j + 3]);
        }
    }
    float* op = out + (size_t)(b0 + b) * T + t0 + c0;
    #pragma unroll
    for (int j = 0; j < 4; ++j) {
        float4 bi = *(const float4*)&bias[t0 + c0 + 4 * j];
        float4 o;
        o.x = fmaf(-Sb, acc[4 * j + 0], bi.x);
        o.y = fmaf(-Sb, acc[4 * j + 1], bi.y);
        o.z = fmaf(-Sb, acc[4 * j + 2], bi.z);
        o.w = fmaf(-Sb, acc[4 * j + 3], bi.w);
        *(float4*)(op + 4 * j) = o;
    }
}

// ---------------- kernel 2: GEMM (tile 128x64, 256 thr, 2 CTAs/SM) ----------
#define A_CSZ  20480                       // 128 rows x 160B (40-word stride)
#define A_BSZ  (2 * A_CSZ)                 // per buf (2 comps)
#define OFF_B  (2 * A_BSZ)                 // 81920
#define B_RST  544
#define B_SZ   (16 * B_RST)                // 8704
#define OFF_V  (OFF_B + 2 * B_SZ)          // 99328: [buf] s[64]
#define V_SZ   256
#define OFF_SB (OFF_V + 2 * V_SZ)          // 99840: S[128]
#define SMEMB  (OFF_SB + 512)              // 100352 (x2 CTAs = 200704)

__device__ __forceinline__ void cp_async16(uint32_t saddr, const void* g) {
    asm volatile("cp.async.cg.shared.global [%0], [%1], 16;" :: "r"(saddr), "l"(g));
}
__device__ __forceinline__ void imma_su(int c[4], uint32_t a0, uint32_t a1,
                                        uint32_t a2, uint32_t a3,
                                        uint32_t b0, uint32_t b1) {
    asm volatile(
        "mma.sync.aligned.m16n8k32.row.col.s32.s8.u8.s32 "
        "{%0,%1,%2,%3}, {%4,%5,%6,%7}, {%8,%9}, {%0,%1,%2,%3};"
        : "+r"(c[0]), "+r"(c[1]), "+r"(c[2]), "+r"(c[3])
        : "r"(a0), "r"(a1), "r"(a2), "r"(a3), "r"(b0), "r"(b1));
}

__global__ void __launch_bounds__(NTH)
qgemm_i8_kernel(const int*   __restrict__ qw,
                const float* __restrict__ scales,
                float*       __restrict__ out,
                int T)
{
    extern __shared__ char smem[];
    const uint32_t sb = (uint32_t)__cvta_generic_to_shared(smem);
    float* smf = (float*)smem;

    const int tid  = threadIdx.x;
    const int warp = tid >> 5;
    const int lane = tid & 31;
    const int r4   = lane >> 2;
    const int kq   = lane & 3;
    const uint32_t sh = (kq & 1) * 4;
    const int wm   = (warp >> 1) * 32;    // 4 m-bands
    const int wn   = (warp & 1) * 32;     // 2 n-bands
    const int m0   = blockIdx.y * 128;
    const int n0   = blockIdx.x * 64;

    auto load_stage = [&](int s, int buf) {
        #pragma unroll
        for (int i = 0; i < 8; ++i) {              // A: 2048 chunks, 8/thread
            int idx  = tid + i * NTH;
            int comp = idx >> 10, rem = idx & 1023;
            int row  = rem >> 3,  j   = rem & 7;
            const uint32_t* src = (comp ? g_xp1 : g_xp0);
            cp_async16(sb + buf * A_BSZ + comp * A_CSZ + row * 160 + j * 16,
                       src + (size_t)(m0 + row) * 1024 + 32 * s + 4 * j);
        }
        {                                          // B: 16 rows x 64 cols words
            int wr = tid >> 4, cq = (tid & 15) * 4;
            cp_async16(sb + OFF_B + buf * B_SZ + wr * B_RST + cq * 4,
                       qw + (size_t)(16 * s + wr) * T + n0 + cq);
        }
        if (tid < 16) {                            // s[64]
            cp_async16(sb + OFF_V + buf * V_SZ + tid * 16,
                       scales + (size_t)s * T + n0 + tid * 4);
        }
        asm volatile("cp.async.commit_group;");
    };

    // ---- prologue ----
    load_stage(0, 0);
    if (tid < 128) smf[OFF_SB / 4 + tid] = g_S[m0 + tid];
    asm volatile("cp.async.wait_group 0;");
    __syncthreads();

    float F[2][4][4];
    #pragma unroll
    for (int mt = 0; mt < 2; ++mt)
        #pragma unroll
        for (int nt = 0; nt < 4; ++nt)
            #pragma unroll
            for (int i = 0; i < 4; ++i) F[mt][nt][i] = 0.f;

    int buf = 0;
    for (int s = 0; s < NSG; ++s) {
        if (s + 1 < NSG) load_stage(s + 1, buf ^ 1);

        const uint32_t baseB = sb + OFF_B + buf * B_SZ;
        const int vf = OFF_V / 4 + buf * (V_SZ / 4);

        // ---- load + extract ALL B fragments once (shared by both comps) ----
        uint32_t bx0[4][4], bx1[4][4];
        #pragma unroll
        for (int kk = 0; kk < 4; ++kk)
            #pragma unroll
            for (int nt = 0; nt < 4; ++nt) {
                const int col = wn + nt * 8 + r4;
                const uint32_t wrd = baseB + (kk * 4 + (kq >> 1)) * B_RST + col * 4;
                uint32_t rw0, rw1;
                asm volatile("ld.shared.b32 %0, [%1];" : "=r"(rw0) : "r"(wrd));
                asm volatile("ld.shared.b32 %0, [%1];" : "=r"(rw1) : "r"(wrd + 2 * B_RST));
                bx0[kk][nt] = (rw0 >> sh) & 0x0F0F0F0Fu;
                bx1[kk][nt] = (rw1 >> sh) & 0x0F0F0F0Fu;
            }

        // per-stage scale vectors (reused by both folds)
        float2 sv[4];
        #pragma unroll
        for (int nt = 0; nt < 4; ++nt)
            sv[nt] = *(const float2*)&smf[vf + wn + nt * 8 + 2 * kq];

        int P[2][4][4];

        #pragma unroll
        for (int comp = 0; comp < 2; ++comp) {
            const uint32_t baseA = sb + buf * A_BSZ + comp * A_CSZ;
            #pragma unroll
            for (int mt = 0; mt < 2; ++mt)
                #pragma unroll
                for (int nt = 0; nt < 4; ++nt)
                    #pragma unroll
                    for (int i = 0; i < 4; ++i) P[mt][nt][i] = 0;

            #pragma unroll
            for (int kk = 0; kk < 4; ++kk) {
                uint32_t a[2][4];
                #pragma unroll
                for (int mt = 0; mt < 2; ++mt) {
                    const uint32_t rowb = baseA +
                        (uint32_t)(wm + mt * 16 + r4) * 160 + kk * 32 + kq * 8;
                    asm volatile("ld.shared.v2.b32 {%0,%1}, [%2];"
                                 : "=r"(a[mt][0]), "=r"(a[mt][2]) : "r"(rowb));
                    asm volatile("ld.shared.v2.b32 {%0,%1}, [%2];"
                                 : "=r"(a[mt][1]), "=r"(a[mt][3]) : "r"(rowb + 8 * 160));
                }
                #pragma unroll
                for (int nt = 0; nt < 4; ++nt) {
                    imma_su(P[0][nt], a[0][0], a[0][1], a[0][2], a[0][3],
                            bx0[kk][nt], bx1[kk][nt]);
                    imma_su(P[1][nt], a[1][0], a[1][1], a[1][2], a[1][3],
                            bx0[kk][nt], bx1[kk][nt]);
                }
            }

            // ---- immediate per-component fold: F += svc * P ----
            const float w254 = comp ? (1.f / 254.f) : 1.f;
            #pragma unroll
            for (int nt = 0; nt < 4; ++nt) {
                const float svx = sv[nt].x * w254;
                const float svy = sv[nt].y * w254;
                #pragma unroll
                for (int mt = 0; mt < 2; ++mt)
                    #pragma unroll
                    for (int h = 0; h < 2; ++h) {
                        F[mt][nt][2 * h]     = fmaf(svx, (float)P[mt][nt][2 * h],
                                                    F[mt][nt][2 * h]);
                        F[mt][nt][2 * h + 1] = fmaf(svy, (float)P[mt][nt][2 * h + 1],
                                                    F[mt][nt][2 * h + 1]);
                    }
            }
        }

        if (s + 1 < NSG) asm volatile("cp.async.wait_group 0;");
        __syncthreads();
        buf ^= 1;
    }

    // ---- output: out = F*Sr + out (corr kernel wrote bias - S*sum sz*Xe) ----
    float Sr[2][2];
    #pragma unroll
    for (int mt = 0; mt < 2; ++mt)
        #pragma unroll
        for (int h = 0; h < 2; ++h)
            Sr[mt][h] = smf[OFF_SB / 4 + wm + mt * 16 + r4 + 8 * h];
    #pragma unroll
    for (int mt = 0; mt < 2; ++mt)
        #pragma unroll
        for (int nt = 0; nt < 4; ++nt)
            #pragma unroll
            for (int h = 0; h < 2; ++h) {
                const int row = m0 + wm + mt * 16 + r4 + 8 * h;
                const int cl  = wn + nt * 8 + 2 * kq;
                float* op = &out[(size_t)row * T + n0 + cl];
                float2 prev = *(float2*)op;
                float2 v;
                v.x = fmaf(F[mt][nt][2 * h + 0], Sr[mt][h], prev.x);
                v.y = fmaf(F[mt][nt][2 * h + 1], Sr[mt][h], prev.y);
                *(float2*)op = v;
            }
}

extern "C" void kernel_launch(void* const* d_in, const int* in_sizes, int n_in,
                              void* d_out, int out_size)
{
    const float* x      = (const float*)d_in[0];
    const int*   qw     = (const int*)  d_in[1];
    const float* scales = (const float*)d_in[2];
    const float* zeros  = (const float*)d_in[3];
    const float* bias   = (const float*)d_in[4];
    float*       out    = (float*)d_out;

    const int T = in_sizes[4];               // 11008

    quant_kernel<<<MDIM, 128>>>(x);

    dim3 cgrid(T / 64, MDIM / 64);           // 172 x 64
    corr_kernel<<<cgrid, 256>>>(scales, zeros, bias, out, T);

    cudaFuncSetAttribute(qgemm_i8_kernel,
                         cudaFuncAttributeMaxDynamicSharedMemorySize, SMEMB);
    dim3 grid(T / 64, MDIM / 128);           // 172 x 32
    qgemm_i8_kernel<<<grid, NTH, SMEMB>>>(qw, scales, out, T);
}

// round 15
// speedup vs baseline: 1.2452x; 1.2452x over previous
#include <cuda_runtime.h>
#include <cstdint>

// ---------------------------------------------------------------------------
// QuantLinear via dual-int8 IMMA (m16n8k32.s8.u8), exact decomposition.
//   x ~= S_b*(x0 + x1/254);  P = 254*P0 + P1 (exact int32, single accumulator)
//   out = Sr * sum_g (s_g/254)*(P_g - z_g*Xtot_g) + bias,  Xtot = 254*X0+X1
// R14 = R12 skeleton + (a) A smem layout [row][kq][kk,half] stride 144B so A
//       frags load as LDS.128 (32 -> 16 issues/warp/stage), (b) coalesced
//       smem-staged quant kernel (~80us -> ~30us).
// ---------------------------------------------------------------------------

#define MDIM 4096
#define KDIM 4096
#define NSG  32
#define NTH  256

__device__ uint32_t g_xp0[MDIM * 1024];
__device__ uint32_t g_xp1[MDIM * 1024];
__device__ float    g_XT[NSG * MDIM];       // 254*X0+X1 per [g][b], exact fp32
__device__ float    g_S[MDIM];

// ---------------- kernel 1: quantize + permute-pack ----------------
__global__ void __launch_bounds__(128)
quant_kernel(const float* __restrict__ x) {
    __shared__ float sx[4224];              // 4096 + skew pads
    __shared__ float red[128];
    __shared__ int   ss0[128], ss1[128];
    const int b = blockIdx.x, tid = threadIdx.x;

    // coalesced load -> skewed smem (word o stored at o + (o>>5))
    const float4* xv = (const float4*)(x + (size_t)b * KDIM);
    #pragma unroll
    for (int i = 0; i < 8; ++i) {
        int idx = tid + i * 128;            // 0..1023 float4s
        float4 f = xv[idx];
        int si = idx * 4 + (idx >> 3);
        sx[si] = f.x; sx[si + 1] = f.y; sx[si + 2] = f.z; sx[si + 3] = f.w;
    }
    __syncthreads();

    float v[32]; float mx = 0.f;
    #pragma unroll
    for (int i = 0; i < 32; ++i) { v[i] = sx[tid * 33 + i]; mx = fmaxf(mx, fabsf(v[i])); }
    red[tid] = mx; __syncthreads();
    for (int o = 64; o > 0; o >>= 1) {
        if (tid < o) red[tid] = fmaxf(red[tid], red[tid + o]);
        __syncthreads();
    }
    const float S    = fmaxf(red[0], 1e-20f) * (1.f / 127.f);
    const float invS = 1.f / S;

    int q0[32], q1[32]; int s0 = 0, s1 = 0;
    #pragma unroll
    for (int i = 0; i < 32; ++i) {
        int a = __float2int_rn(v[i] * invS);
        a = max(-127, min(127, a));
        float r = v[i] - S * (float)a;
        int c = __float2int_rn(r * (254.f * invS));
        c = max(-127, min(127, c));
        q0[i] = a; q1[i] = c; s0 += a; s1 += c;
    }
    // NEW word order within a 32-word stage row: word = kq*8 + kk*2 + half.
    // This thread covers stage = tid>>2, kk = tid&3. Byte content per (kq,half)
    // unchanged: byte j <- local k = (kq>>1)*8 + (kq&1) + 2j + 16*half.
    const uint32_t rowbase = (uint32_t)b * 1024u + (uint32_t)(tid >> 2) * 32u
                           + (uint32_t)(tid & 3) * 2u;
    #pragma unroll
    for (int kq = 0; kq < 4; ++kq) {
        #pragma unroll
        for (int half = 0; half < 2; ++half) {
            const int k0 = (kq >> 1) * 8 + (kq & 1) + 16 * half;
            uint32_t u0 = 0, u1 = 0;
            #pragma unroll
            for (int j = 0; j < 4; ++j) {
                u0 |= (uint32_t)(q0[k0 + 2 * j] & 255) << (8 * j);
                u1 |= (uint32_t)(q1[k0 + 2 * j] & 255) << (8 * j);
            }
            g_xp0[rowbase + kq * 8 + half] = u0;
            g_xp1[rowbase + kq * 8 + half] = u1;
        }
    }
    ss0[tid] = s0; ss1[tid] = s1; __syncthreads();
    if (tid < 32) {
        int X0 = ss0[4 * tid] + ss0[4 * tid + 1] + ss0[4 * tid + 2] + ss0[4 * tid + 3];
        int X1 = ss1[4 * tid] + ss1[4 * tid + 1] + ss1[4 * tid + 2] + ss1[4 * tid + 3];
        g_XT[tid * MDIM + b] = (float)(254 * X0 + X1);
    }
    if (tid == 0) g_S[b] = S;
}

// ---------------- kernel 2: GEMM (tile 128x64, 256 thr, 2 CTAs/SM) ----------
#define A_CSZ  18432                       // 128 rows x 144B (36-word stride)
#define A_BSZ  (2 * A_CSZ)                 // per buf (2 comps) = 36864
#define OFF_B  (2 * A_BSZ)                 // 73728
#define B_RST  544
#define B_SZ   (16 * B_RST)                // 8704
#define OFF_V  (OFF_B + 2 * B_SZ)          // 91136: [buf] s[64] z[64] Xt[128]
#define V_SZ   1024
#define OFF_SB (OFF_V + 2 * V_SZ)          // 93184: S[128] bias[64]
#define SMEMB  (OFF_SB + 768)              // 93952  (x2 CTAs = 187904 <= SM)

__device__ __forceinline__ void cp_async16(uint32_t saddr, const void* g) {
    asm volatile("cp.async.cg.shared.global [%0], [%1], 16;" :: "r"(saddr), "l"(g));
}
__device__ __forceinline__ void imma_su(int c[4], uint32_t a0, uint32_t a1,
                                        uint32_t a2, uint32_t a3,
                                        uint32_t b0, uint32_t b1) {
    asm volatile(
        "mma.sync.aligned.m16n8k32.row.col.s32.s8.u8.s32 "
        "{%0,%1,%2,%3}, {%4,%5,%6,%7}, {%8,%9}, {%0,%1,%2,%3};"
        : "+r"(c[0]), "+r"(c[1]), "+r"(c[2]), "+r"(c[3])
        : "r"(a0), "r"(a1), "r"(a2), "r"(a3), "r"(b0), "r"(b1));
}

__global__ void __launch_bounds__(NTH)
qgemm_i8_kernel(const int*   __restrict__ qw,
                const float* __restrict__ scales,
                const float* __restrict__ zeros,
                const float* __restrict__ bias,
                float*       __restrict__ out,
                int T)
{
    extern __shared__ char smem[];
    const uint32_t sb = (uint32_t)__cvta_generic_to_shared(smem);
    float* smf = (float*)smem;

    const int tid  = threadIdx.x;
    const int warp = tid >> 5;
    const int lane = tid & 31;
    const int r4   = lane >> 2;
    const int kq   = lane & 3;
    const uint32_t sh = (kq & 1) * 4;
    const int wm   = (warp >> 1) * 32;    // 4 m-bands
    const int wn   = (warp & 1) * 32;     // 2 n-bands
    const int m0   = blockIdx.y * 128;
    const int n0   = blockIdx.x * 64;

    auto load_stage = [&](int s, int buf) {
        #pragma unroll
        for (int i = 0; i < 8; ++i) {              // A: 2048 chunks, 8/thread
            int idx  = tid + i * NTH;
            int comp = idx >> 10, rem = idx & 1023;
            int row  = rem >> 3,  j   = rem & 7;
            const uint32_t* src = (comp ? g_xp1 : g_xp0);
            cp_async16(sb + buf * A_BSZ + comp * A_CSZ + row * 144 + j * 16,
                       src + (size_t)(m0 + row) * 1024 + 32 * s + 4 * j);
        }
        {                                          // B: 16 rows x 64 cols words
            int wr = tid >> 4, cq = (tid & 15) * 4;
            cp_async16(sb + OFF_B + buf * B_SZ + wr * B_RST + cq * 4,
                       qw + (size_t)(16 * s + wr) * T + n0 + cq);
        }
        if (tid < 64) {                            // vectors s[64] z[64] Xt[128]
            int a = tid >> 4;
            if (a == 0) {
                int o = (tid & 15) * 4;
                cp_async16(sb + OFF_V + buf * V_SZ + o * 4,
                           scales + (size_t)s * T + n0 + o);
            } else if (a == 1) {
                int o = (tid & 15) * 4;
                cp_async16(sb + OFF_V + buf * V_SZ + 256 + o * 4,
                           zeros + (size_t)s * T + n0 + o);
            } else {
                int o = (tid - 32) * 4;            // 0..124
                cp_async16(sb + OFF_V + buf * V_SZ + 512 + o * 4,
                           g_XT + (size_t)s * MDIM + m0 + o);
            }
        }
        asm volatile("cp.async.commit_group;");
    };

    // ---- prologue ----
    load_stage(0, 0);
    if (tid < 128)       smf[OFF_SB / 4 + tid] = g_S[m0 + tid];
    else if (tid < 192)  smf[OFF_SB / 4 + tid] = bias[n0 + (tid - 128)];
    asm volatile("cp.async.wait_group 0;");
    __syncthreads();

    float F[2][4][4];
    #pragma unroll
    for (int mt = 0; mt < 2; ++mt)
        #pragma unroll
        for (int nt = 0; nt < 4; ++nt)
            #pragma unroll
            for (int i = 0; i < 4; ++i) F[mt][nt][i] = 0.f;

    int buf = 0;
    for (int s = 0; s < NSG; ++s) {
        if (s + 1 < NSG) load_stage(s + 1, buf ^ 1);

        const uint32_t baseB = sb + OFF_B + buf * B_SZ;
        const int vf = OFF_V / 4 + buf * (V_SZ / 4);

        // ---- load + extract ALL B fragments once (shared by both comps) ----
        uint32_t bx0[4][4], bx1[4][4];
        #pragma unroll
        for (int kk = 0; kk < 4; ++kk)
            #pragma unroll
            for (int nt = 0; nt < 4; ++nt) {
                const int col = wn + nt * 8 + r4;
                const uint32_t wrd = baseB + (kk * 4 + (kq >> 1)) * B_RST + col * 4;
                uint32_t rw0, rw1;
                asm volatile("ld.shared.b32 %0, [%1];" : "=r"(rw0) : "r"(wrd));
                asm volatile("ld.shared.b32 %0, [%1];" : "=r"(rw1) : "r"(wrd + 2 * B_RST));
                bx0[kk][nt] = (rw0 >> sh) & 0x0F0F0F0Fu;
                bx1[kk][nt] = (rw1 >> sh) & 0x0F0F0F0Fu;
            }

        int P[2][4][4];
        #pragma unroll
        for (int mt = 0; mt < 2; ++mt)
            #pragma unroll
            for (int nt = 0; nt < 4; ++nt)
                #pragma unroll
                for (int i = 0; i < 4; ++i) P[mt][nt][i] = 0;

        #pragma unroll
        for (int comp = 0; comp < 2; ++comp) {
            const uint32_t baseA = sb + buf * A_BSZ + comp * A_CSZ;
            if (comp == 1) {             // P = 254*P0, then comp1 accumulates
                #pragma unroll
                for (int mt = 0; mt < 2; ++mt)
                    #pragma unroll
                    for (int nt = 0; nt < 4; ++nt)
                        #pragma unroll
                        for (int i = 0; i < 4; ++i) P[mt][nt][i] *= 254;
            }
            #pragma unroll
            for (int kh = 0; kh < 2; ++kh) {       // 2 k-steps per LDS.128
                uint32_t q[2][2][4];               // [mt][rowhalf][word]
                #pragma unroll
                for (int mt = 0; mt < 2; ++mt) {
                    const uint32_t rowb = baseA +
                        (uint32_t)(wm + mt * 16 + r4) * 144 + kq * 32 + kh * 16;
                    asm volatile("ld.shared.v4.b32 {%0,%1,%2,%3}, [%4];"
                                 : "=r"(q[mt][0][0]), "=r"(q[mt][0][1]),
                                   "=r"(q[mt][0][2]), "=r"(q[mt][0][3])
                                 : "r"(rowb));
                    asm volatile("ld.shared.v4.b32 {%0,%1,%2,%3}, [%4];"
                                 : "=r"(q[mt][1][0]), "=r"(q[mt][1][1]),
                                   "=r"(q[mt][1][2]), "=r"(q[mt][1][3])
                                 : "r"(rowb + 8 * 144));
                }
                #pragma unroll
                for (int kj = 0; kj < 2; ++kj) {
                    const int kk = 2 * kh + kj;
                    #pragma unroll
                    for (int nt = 0; nt < 4; ++nt) {
                        imma_su(P[0][nt], q[0][0][2 * kj], q[0][1][2 * kj],
                                q[0][0][2 * kj + 1], q[0][1][2 * kj + 1],
                                bx0[kk][nt], bx1[kk][nt]);
                        imma_su(P[1][nt], q[1][0][2 * kj], q[1][1][2 * kj],
                                q[1][0][2 * kj + 1], q[1][1][2 * kj + 1],
                                bx0[kk][nt], bx1[kk][nt]);
                    }
                }
            }
        }

        // ---- per-group fold: F += (s/254)*(P - z*Xtot) ----
        {
            float Xr[2][2];
            #pragma unroll
            for (int mt = 0; mt < 2; ++mt)
                #pragma unroll
                for (int h = 0; h < 2; ++h)
                    Xr[mt][h] = smf[vf + 128 + wm + mt * 16 + r4 + 8 * h];
            #pragma unroll
            for (int nt = 0; nt < 4; ++nt) {
                const int cl0 = wn + nt * 8 + 2 * kq;
                const float2 sv2 = *(const float2*)&smf[vf + cl0];
                const float2 zv2 = *(const float2*)&smf[vf + 64 + cl0];
                const float svx = sv2.x * (1.f / 254.f);
                const float svy = sv2.y * (1.f / 254.f);
                #pragma unroll
                for (int mt = 0; mt < 2; ++mt)
                    #pragma unroll
                    for (int h = 0; h < 2; ++h) {
                        float t0 = fmaf(-zv2.x, Xr[mt][h], (float)P[mt][nt][2 * h]);
                        float t1 = fmaf(-zv2.y, Xr[mt][h], (float)P[mt][nt][2 * h + 1]);
                        F[mt][nt][2 * h]     = fmaf(svx, t0, F[mt][nt][2 * h]);
                        F[mt][nt][2 * h + 1] = fmaf(svy, t1, F[mt][nt][2 * h + 1]);
                    }
            }
        }

        if (s + 1 < NSG) asm volatile("cp.async.wait_group 0;");
        __syncthreads();
        buf ^= 1;
    }

    // ---- output: out = F*Sr + bias ----
    float Sr[2][2];
    #pragma unroll
    for (int mt = 0; mt < 2; ++mt)
        #pragma unroll
        for (int h = 0; h < 2; ++h)
            Sr[mt][h] = smf[OFF_SB / 4 + wm + mt * 16 + r4 + 8 * h];
    #pragma unroll
    for (int mt = 0; mt < 2; ++mt)
        #pragma unroll
        for (int nt = 0; nt < 4; ++nt)
            #pragma unroll
            for (int h = 0; h < 2; ++h) {
                const int row = m0 + wm + mt * 16 + r4 + 8 * h;
                const int cl  = wn + nt * 8 + 2 * kq;
                float2 v;
                v.x = fmaf(F[mt][nt][2 * h + 0], Sr[mt][h], smf[OFF_SB / 4 + 128 + cl]);
                v.y = fmaf(F[mt][nt][2 * h + 1], Sr[mt][h], smf[OFF_SB / 4 + 128 + cl + 1]);
                *(float2*)&out[(size_t)row * T + n0 + cl] = v;
            }
}

extern "C" void kernel_launch(void* const* d_in, const int* in_sizes, int n_in,
                              void* d_out, int out_size)
{
    const float* x      = (const float*)d_in[0];
    const int*   qw     = (const int*)  d_in[1];
    const float* scales = (const float*)d_in[2];
    const float* zeros  = (const float*)d_in[3];
    const float* bias   = (const float*)d_in[4];
    float*       out    = (float*)d_out;

    const int T = in_sizes[4];               // 11008

    quant_kernel<<<MDIM, 128>>>(x);

    cudaFuncSetAttribute(qgemm_i8_kernel,
                         cudaFuncAttributeMaxDynamicSharedMemorySize, SMEMB);
    dim3 grid(T / 64, MDIM / 128);           // 172 x 32
    qgemm_i8_kernel<<<grid, NTH, SMEMB>>>(qw, scales, zeros, bias, out, T);
}

// round 17
// speedup vs baseline: 1.6240x; 1.3042x over previous
#include <cuda_runtime.h>
#include <cstdint>

// ---------------------------------------------------------------------------
// QuantLinear via dual-int8 IMMA (m16n8k32.s8.u8), exact decomposition.
//   x ~= S_b*(x0 + x1/254);  P = 254*P0 + P1 (exact int32, single accumulator)
//   out = Sr * sum_g (s_g/254)*(P_g - z_g*Xtot_g) + bias,  Xtot = 254*X0+X1
// R17 = R12 GEMM byte-identical (proven 1430us) + quant kernel coalescing fix
//       (smem-staged input read; pack logic & layout unchanged from R12).
// ---------------------------------------------------------------------------

#define MDIM 4096
#define KDIM 4096
#define NSG  32
#define NTH  256

__device__ uint32_t g_xp0[MDIM * 1024];
__device__ uint32_t g_xp1[MDIM * 1024];
__device__ float    g_XT[NSG * MDIM];       // 254*X0+X1 per [g][b], exact fp32
__device__ float    g_S[MDIM];

// ---------------- kernel 1: quantize + permute-pack ----------------
__global__ void __launch_bounds__(128)
quant_kernel(const float* __restrict__ x) {
    __shared__ float sx[4224];              // 4096 + skew pads
    __shared__ float red[128];
    __shared__ int   ss0[128], ss1[128];
    const int b = blockIdx.x, tid = threadIdx.x;

    // coalesced float4 load -> skewed smem (float4 idx stored at idx*4+(idx>>3))
    const float4* xv = (const float4*)(x + (size_t)b * KDIM);
    #pragma unroll
    for (int i = 0; i < 8; ++i) {
        int idx = tid + i * 128;            // 0..1023 float4s
        float4 f = xv[idx];
        int si = idx * 4 + (idx >> 3);
        sx[si] = f.x; sx[si + 1] = f.y; sx[si + 2] = f.z; sx[si + 3] = f.w;
    }
    __syncthreads();

    // this thread's 32 consecutive floats live at sx[tid*33 .. tid*33+32]
    // (8 float4 groups of 4+pad-every-8-words => base tid*32 + tid*1 = tid*33,
    //  within the group of 8 floats stride is contiguous, +1 pad each 8)
    float v[32]; float mx = 0.f;
    #pragma unroll
    for (int i = 0; i < 32; ++i) {
        int o = tid * 32 + i;
        v[i] = sx[o + (o >> 5)];
        mx = fmaxf(mx, fabsf(v[i]));
    }
    red[tid] = mx; __syncthreads();
    for (int o = 64; o > 0; o >>= 1) {
        if (tid < o) red[tid] = fmaxf(red[tid], red[tid + o]);
        __syncthreads();
    }
    const float S    = fmaxf(red[0], 1e-20f) * (1.f / 127.f);
    const float invS = 1.f / S;

    int q0[32], q1[32]; int s0 = 0, s1 = 0;
    #pragma unroll
    for (int i = 0; i < 32; ++i) {
        int a = __float2int_rn(v[i] * invS);
        a = max(-127, min(127, a));
        float r = v[i] - S * (float)a;
        int c = __float2int_rn(r * (254.f * invS));
        c = max(-127, min(127, c));
        q0[i] = a; q1[i] = c; s0 += a; s1 += c;
    }
    // R12 word order: w' = kq*2 + half; byte j <- local k =
    //   (kq>>1)*8 + (kq&1) + 2j + 16*half
    const uint32_t base = (uint32_t)b * 1024u + tid * 8u;
    #pragma unroll
    for (int w = 0; w < 8; ++w) {
        const int kq = w >> 1, half = w & 1;
        const int k0 = (kq >> 1) * 8 + (kq & 1) + 16 * half;
        uint32_t u0 = 0, u1 = 0;
        #pragma unroll
        for (int j = 0; j < 4; ++j) {
            u0 |= (uint32_t)(q0[k0 + 2 * j] & 255) << (8 * j);
            u1 |= (uint32_t)(q1[k0 + 2 * j] & 255) << (8 * j);
        }
        g_xp0[base + w] = u0; g_xp1[base + w] = u1;
    }
    ss0[tid] = s0; ss1[tid] = s1; __syncthreads();
    if (tid < 32) {
        int X0 = ss0[4 * tid] + ss0[4 * tid + 1] + ss0[4 * tid + 2] + ss0[4 * tid + 3];
        int X1 = ss1[4 * tid] + ss1[4 * tid + 1] + ss1[4 * tid + 2] + ss1[4 * tid + 3];
        g_XT[tid * MDIM + b] = (float)(254 * X0 + X1);
    }
    if (tid == 0) g_S[b] = S;
}

// ---------------- kernel 2: GEMM (tile 128x64, 256 thr, 2 CTAs/SM) ----------
#define A_CSZ  20480                       // 128 rows x 160B (40-word stride)
#define A_BSZ  (2 * A_CSZ)                 // per buf (2 comps)
#define OFF_B  (2 * A_BSZ)                 // 81920
#define B_RST  544                         // 8-bank krow offset (conflict-free)
#define B_SZ   (16 * B_RST)                // 8704
#define OFF_V  (OFF_B + 2 * B_SZ)          // 99328: [buf] s[64] z[64] Xt[128]
#define V_SZ   1024
#define OFF_SB (OFF_V + 2 * V_SZ)          // 101376: S[128] bias[64]
#define SMEMB  (OFF_SB + 768)              // 102144  (x2 CTAs = 204288 <= SM)

__device__ __forceinline__ void cp_async16(uint32_t saddr, const void* g) {
    asm volatile("cp.async.cg.shared.global [%0], [%1], 16;" :: "r"(saddr), "l"(g));
}
__device__ __forceinline__ void imma_su(int c[4], uint32_t a0, uint32_t a1,
                                        uint32_t a2, uint32_t a3,
                                        uint32_t b0, uint32_t b1) {
    asm volatile(
        "mma.sync.aligned.m16n8k32.row.col.s32.s8.u8.s32 "
        "{%0,%1,%2,%3}, {%4,%5,%6,%7}, {%8,%9}, {%0,%1,%2,%3};"
        : "+r"(c[0]), "+r"(c[1]), "+r"(c[2]), "+r"(c[3])
        : "r"(a0), "r"(a1), "r"(a2), "r"(a3), "r"(b0), "r"(b1));
}

__global__ void __launch_bounds__(NTH)
qgemm_i8_kernel(const int*   __restrict__ qw,
                const float* __restrict__ scales,
                const float* __restrict__ zeros,
                const float* __restrict__ bias,
                float*       __restrict__ out,
                int T)
{
    extern __shared__ char smem[];
    const uint32_t sb = (uint32_t)__cvta_generic_to_shared(smem);
    float* smf = (float*)smem;

    const int tid  = threadIdx.x;
    const int warp = tid >> 5;
    const int lane = tid & 31;
    const int r4   = lane >> 2;
    const int kq   = lane & 3;
    const uint32_t sh = (kq & 1) * 4;
    const int wm   = (warp >> 1) * 32;    // 4 m-bands
    const int wn   = (warp & 1) * 32;     // 2 n-bands
    const int m0   = blockIdx.y * 128;
    const int n0   = blockIdx.x * 64;

    auto load_stage = [&](int s, int buf) {
        #pragma unroll
        for (int i = 0; i < 8; ++i) {              // A: 2048 chunks, 8/thread
            int idx  = tid + i * NTH;
            int comp = idx >> 10, rem = idx & 1023;
            int row  = rem >> 3,  j   = rem & 7;
            const uint32_t* src = (comp ? g_xp1 : g_xp0);
            cp_async16(sb + buf * A_BSZ + comp * A_CSZ + row * 160 + j * 16,
                       src + (size_t)(m0 + row) * 1024 + 32 * s + 4 * j);
        }
        {                                          // B: 16 rows x 64 cols words
            int wr = tid >> 4, cq = (tid & 15) * 4;
            cp_async16(sb + OFF_B + buf * B_SZ + wr * B_RST + cq * 4,
                       qw + (size_t)(16 * s + wr) * T + n0 + cq);
        }
        if (tid < 64) {                            // vectors s[64] z[64] Xt[128]
            int a = tid >> 4;
            if (a == 0) {
                int o = (tid & 15) * 4;
                cp_async16(sb + OFF_V + buf * V_SZ + o * 4,
                           scales + (size_t)s * T + n0 + o);
            } else if (a == 1) {
                int o = (tid & 15) * 4;
                cp_async16(sb + OFF_V + buf * V_SZ + 256 + o * 4,
                           zeros + (size_t)s * T + n0 + o);
            } else {
                int o = (tid - 32) * 4;            // 0..124
                cp_async16(sb + OFF_V + buf * V_SZ + 512 + o * 4,
                           g_XT + (size_t)s * MDIM + m0 + o);
            }
        }
        asm volatile("cp.async.commit_group;");
    };

    // ---- prologue ----
    load_stage(0, 0);
    if (tid < 128)       smf[OFF_SB / 4 + tid] = g_S[m0 + tid];
    else if (tid < 192)  smf[OFF_SB / 4 + tid] = bias[n0 + (tid - 128)];
    asm volatile("cp.async.wait_group 0;");
    __syncthreads();

    float F[2][4][4];
    #pragma unroll
    for (int mt = 0; mt < 2; ++mt)
        #pragma unroll
        for (int nt = 0; nt < 4; ++nt)
            #pragma unroll
            for (int i = 0; i < 4; ++i) F[mt][nt][i] = 0.f;

    int buf = 0;
    for (int s = 0; s < NSG; ++s) {
        if (s + 1 < NSG) load_stage(s + 1, buf ^ 1);

        const uint32_t baseB = sb + OFF_B + buf * B_SZ;
        const int vf = OFF_V / 4 + buf * (V_SZ / 4);

        // ---- load + extract ALL B fragments once (shared by both comps) ----
        uint32_t bx0[4][4], bx1[4][4];
        #pragma unroll
        for (int kk = 0; kk < 4; ++kk)
            #pragma unroll
            for (int nt = 0; nt < 4; ++nt) {
                const int col = wn + nt * 8 + r4;
                const uint32_t wrd = baseB + (kk * 4 + (kq >> 1)) * B_RST + col * 4;
                uint32_t rw0, rw1;
                asm volatile("ld.shared.b32 %0, [%1];" : "=r"(rw0) : "r"(wrd));
                asm volatile("ld.shared.b32 %0, [%1];" : "=r"(rw1) : "r"(wrd + 2 * B_RST));
                bx0[kk][nt] = (rw0 >> sh) & 0x0F0F0F0Fu;
                bx1[kk][nt] = (rw1 >> sh) & 0x0F0F0F0Fu;
            }

        int P[2][4][4];
        #pragma unroll
        for (int mt = 0; mt < 2; ++mt)
            #pragma unroll
            for (int nt = 0; nt < 4; ++nt)
                #pragma unroll
                for (int i = 0; i < 4; ++i) P[mt][nt][i] = 0;

        #pragma unroll
        for (int comp = 0; comp < 2; ++comp) {
            const uint32_t baseA = sb + buf * A_BSZ + comp * A_CSZ;
            if (comp == 1) {             // P = 254*P0, then comp1 accumulates
                #pragma unroll
                for (int mt = 0; mt < 2; ++mt)
                    #pragma unroll
                    for (int nt = 0; nt < 4; ++nt)
                        #pragma unroll
                        for (int i = 0; i < 4; ++i) P[mt][nt][i] *= 254;
            }
            #pragma unroll
            for (int kk = 0; kk < 4; ++kk) {
                uint32_t a[2][4];
                #pragma unroll
                for (int mt = 0; mt < 2; ++mt) {
                    const uint32_t rowb = baseA +
                        (uint32_t)(wm + mt * 16 + r4) * 160 + kk * 32 + kq * 8;
                    asm volatile("ld.shared.v2.b32 {%0,%1}, [%2];"
                                 : "=r"(a[mt][0]), "=r"(a[mt][2]) : "r"(rowb));
                    asm volatile("ld.shared.v2.b32 {%0,%1}, [%2];"
                                 : "=r"(a[mt][1]), "=r"(a[mt][3]) : "r"(rowb + 8 * 160));
                }
                #pragma unroll
                for (int nt = 0; nt < 4; ++nt) {
                    imma_su(P[0][nt], a[0][0], a[0][1], a[0][2], a[0][3],
                            bx0[kk][nt], bx1[kk][nt]);
                    imma_su(P[1][nt], a[1][0], a[1][1], a[1][2], a[1][3],
                            bx0[kk][nt], bx1[kk][nt]);
                }
            }
        }

        // ---- per-group fold: F += (s/254)*(P - z*Xtot) ----
        {
            float Xr[2][2];
            #pragma unroll
            for (int mt = 0; mt < 2; ++mt)
                #pragma unroll
                for (int h = 0; h < 2; ++h)
                    Xr[mt][h] = smf[vf + 128 + wm + mt * 16 + r4 + 8 * h];
            #pragma unroll
            for (int nt = 0; nt < 4; ++nt) {
                const int cl0 = wn + nt * 8 + 2 * kq;
                const float2 sv2 = *(const float2*)&smf[vf + cl0];
                const float2 zv2 = *(const float2*)&smf[vf + 64 + cl0];
                const float svx = sv2.x * (1.f / 254.f);
                const float svy = sv2.y * (1.f / 254.f);
                #pragma unroll
                for (int mt = 0; mt < 2; ++mt)
                    #pragma unroll
                    for (int h = 0; h < 2; ++h) {
                        float t0 = fmaf(-zv2.x, Xr[mt][h], (float)P[mt][nt][2 * h]);
                        float t1 = fmaf(-zv2.y, Xr[mt][h], (float)P[mt][nt][2 * h + 1]);
                        F[mt][nt][2 * h]     = fmaf(svx, t0, F[mt][nt][2 * h]);
                        F[mt][nt][2 * h + 1] = fmaf(svy, t1, F[mt][nt][2 * h + 1]);
                    }
            }
        }

        if (s + 1 < NSG) asm volatile("cp.async.wait_group 0;");
        __syncthreads();
        buf ^= 1;
    }

    // ---- output: out = F*Sr + bias ----
    float Sr[2][2];
    #pragma unroll
    for (int mt = 0; mt < 2; ++mt)
        #pragma unroll
        for (int h = 0; h < 2; ++h)
            Sr[mt][h] = smf[OFF_SB / 4 + wm + mt * 16 + r4 + 8 * h];
    #pragma unroll
    for (int mt = 0; mt < 2; ++mt)
        #pragma unroll
        for (int nt = 0; nt < 4; ++nt)
            #pragma unroll
            for (int h = 0; h < 2; ++h) {
                const int row = m0 + wm + mt * 16 + r4 + 8 * h;
                const int cl  = wn + nt * 8 + 2 * kq;
                float2 v;
                v.x = fmaf(F[mt][nt][2 * h + 0], Sr[mt][h], smf[OFF_SB / 4 + 128 + cl]);
                v.y = fmaf(F[mt][nt][2 * h + 1], Sr[mt][h], smf[OFF_SB / 4 + 128 + cl + 1]);
                *(float2*)&out[(size_t)row * T + n0 + cl] = v;
            }
}

extern "C" void kernel_launch(void* const* d_in, const int* in_sizes, int n_in,
                              void* d_out, int out_size)
{
    const float* x      = (const float*)d_in[0];
    const int*   qw     = (const int*)  d_in[1];
    const float* scales = (const float*)d_in[2];
    const float* zeros  = (const float*)d_in[3];
    const float* bias   = (const float*)d_in[4];
    float*       out    = (float*)d_out;

    const int T = in_sizes[4];               // 11008

    quant_kernel<<<MDIM, 128>>>(x);

    cudaFuncSetAttribute(qgemm_i8_kernel,
                         cudaFuncAttributeMaxDynamicSharedMemorySize, SMEMB);
    dim3 grid(T / 64, MDIM / 128);           // 172 x 32
    qgemm_i8_kernel<<<grid, NTH, SMEMB>>>(qw, scales, zeros, bias, out, T);
}